// round 16
// baseline (speedup 1.0000x reference)
#include <cuda_runtime.h>
#include <cuda_bf16.h>
#include <math.h>
#include <cstdint>

// GhostVLAD — round 15 (sm_103a). N=32, C=512, P=1024, KG=10, KV=8.
// Proven-best trio with K1 prologue/tail trims:
//   K1: R8 fused logits+softmax (occ4, 64 regs) + div-free wd fill + smem bias.
//   K2: R5 ax GEMM + residual + sumsq partials.
//   K3: R5 normalize. (Fusion attempts failed twice: launch floor < reg pollution.)

#define N_   32
#define C_   512
#define P_   1024
#define KG_  10
#define KV_  8
#define PC1_ 64                  // pixels per K1 CTA
#define NCH_ 16                  // K1 chunks per image

typedef unsigned long long u64_t;

__device__ __forceinline__ u64_t pack2(float lo, float hi) {
    u64_t r; asm("mov.b64 %0, {%1, %2};" : "=l"(r) : "f"(lo), "f"(hi)); return r;
}
__device__ __forceinline__ void unpack2(u64_t v, float& lo, float& hi) {
    asm("mov.b64 {%0, %1}, %2;" : "=f"(lo), "=f"(hi) : "l"(v));
}
__device__ __forceinline__ void fma2(u64_t& d, u64_t a, u64_t b) {
    asm("fma.rn.f32x2 %0, %1, %2, %0;" : "+l"(d) : "l"(a), "l"(b));
}

// scratch
__device__ float g_a[N_ * KV_ * P_];            // [n][k][p]
__device__ float g_asum[N_ * NCH_ * KV_];       // [n][chunk][k]
__device__ float g_r[N_ * KV_ * C_];            // residuals [n][k][c]
__device__ float g_ss[N_ * KV_ * 16];           // sumsq partials [n][k][cc]

// ---------------- K1: logits + softmax ----------------
// warp: 2 channel-slices (lane>>4) x 16 pixel-quads (lane&15); 8 warps -> 16 slices.
__global__ __launch_bounds__(256, 4) void gv_K1(
    const float* __restrict__ x, const float* __restrict__ w,
    const float* __restrict__ bias)
{
    __shared__ u64_t wd[C_ * 6];                 // 24KB: [c][kp] = (w[2kp], w[2kp+1])
    __shared__ float red[KG_ * 8 * PC1_];        // 20KB: [k][csh][p]
    __shared__ float asb[2][KV_];
    __shared__ float bias_s[KG_];

    const int pc = blockIdx.x;       // 0..15
    const int n  = blockIdx.y;
    const int t  = threadIdx.x;
    const int wid  = t >> 5;
    const int lane = t & 31;
    const int pq = lane & 15;               // pixel quad 0..15
    const int cs = wid * 2 + (lane >> 4);   // channel slice 0..15 (32 ch each)

    // div-free wd fill: 2 passes over c, kp unrolled; coalesced w reads
    #pragma unroll
    for (int cp0 = 0; cp0 < C_; cp0 += 256) {
        const int c = cp0 + t;
        #pragma unroll
        for (int kp = 0; kp < 5; ++kp)
            wd[c * 6 + kp] = pack2(w[(2 * kp) * C_ + c], w[(2 * kp + 1) * C_ + c]);
    }
    if (t < KG_) bias_s[t] = bias[t];
    __syncthreads();

    const int p_base = pc * PC1_ + 4 * pq;
    const float* xp = x + ((size_t)n * C_ + cs * 32) * P_ + p_base;

    // acc[kp][px] = (logit_{2kp}(px), logit_{2kp+1}(px)) : 40 registers
    u64_t acc[5][4];
    #pragma unroll
    for (int kp = 0; kp < 5; ++kp)
        #pragma unroll
        for (int px = 0; px < 4; ++px) acc[kp][px] = pack2(0.f, 0.f);

    #pragma unroll
    for (int b = 0; b < 8; ++b) {
        #pragma unroll
        for (int j = 0; j < 4; ++j) {
            const float4 xv = *(const float4*)(xp + (size_t)(b * 4 + j) * P_);
            const int c = cs * 32 + b * 4 + j;
            const ulonglong2* wr2 = (const ulonglong2*)(wd + c * 6);
            ulonglong2 w01 = wr2[0];
            ulonglong2 w23 = wr2[1];
            u64_t w4 = wd[c * 6 + 4];
            u64_t xd[4];
            xd[0] = pack2(xv.x, xv.x);
            xd[1] = pack2(xv.y, xv.y);
            xd[2] = pack2(xv.z, xv.z);
            xd[3] = pack2(xv.w, xv.w);
            #pragma unroll
            for (int px = 0; px < 4; ++px) {
                fma2(acc[0][px], xd[px], w01.x);
                fma2(acc[1][px], xd[px], w01.y);
                fma2(acc[2][px], xd[px], w23.x);
                fma2(acc[3][px], xd[px], w23.y);
                fma2(acc[4][px], xd[px], w4);
            }
        }
    }

    // two-phase cross-slice reduction in smem (16 slices -> 8)
    if (cs >= 8) {
        #pragma unroll
        for (int kp = 0; kp < 5; ++kp) {
            float4 lo4, hi4;
            unpack2(acc[kp][0], lo4.x, hi4.x);
            unpack2(acc[kp][1], lo4.y, hi4.y);
            unpack2(acc[kp][2], lo4.z, hi4.z);
            unpack2(acc[kp][3], lo4.w, hi4.w);
            *(float4*)(red + ((2 * kp) * 8 + cs - 8) * PC1_ + 4 * pq)     = lo4;
            *(float4*)(red + ((2 * kp + 1) * 8 + cs - 8) * PC1_ + 4 * pq) = hi4;
        }
    }
    __syncthreads();
    if (cs < 8) {
        #pragma unroll
        for (int kp = 0; kp < 5; ++kp) {
            float4* plo = (float4*)(red + ((2 * kp) * 8 + cs) * PC1_ + 4 * pq);
            float4* phi = (float4*)(red + ((2 * kp + 1) * 8 + cs) * PC1_ + 4 * pq);
            float4 lo4 = *plo, hi4 = *phi;
            float a0, a1;
            unpack2(acc[kp][0], a0, a1); lo4.x += a0; hi4.x += a1;
            unpack2(acc[kp][1], a0, a1); lo4.y += a0; hi4.y += a1;
            unpack2(acc[kp][2], a0, a1); lo4.z += a0; hi4.z += a1;
            unpack2(acc[kp][3], a0, a1); lo4.w += a0; hi4.w += a1;
            *plo = lo4; *phi = hi4;
        }
    }
    __syncthreads();

    // softmax per pixel: threads 0..63, p = t
    if (t < PC1_) {
        const int p = t;
        const int lane2 = t & 31, wid2 = t >> 5;
        float lg[KG_];
        #pragma unroll
        for (int k = 0; k < KG_; ++k) {
            float s = 0.f;
            #pragma unroll
            for (int c8 = 0; c8 < 8; ++c8) s += red[(k * 8 + c8) * PC1_ + p];
            lg[k] = s + bias_s[k];
        }
        float m = lg[0];
        #pragma unroll
        for (int k = 1; k < KG_; ++k) m = fmaxf(m, lg[k]);
        float e[KG_], ssum = 0.f;
        #pragma unroll
        for (int k = 0; k < KG_; ++k) { e[k] = __expf(lg[k] - m); ssum += e[k]; }
        float inv = 1.0f / ssum;

        #pragma unroll
        for (int k = 0; k < KV_; ++k) {
            float a = e[k] * inv;
            g_a[((size_t)n * KV_ + k) * P_ + pc * PC1_ + p] = a;
            float v = a;
            #pragma unroll
            for (int o = 16; o; o >>= 1) v += __shfl_xor_sync(0xffffffffu, v, o);
            if (lane2 == 0) asb[wid2][k] = v;
        }
    }
    __syncthreads();
    if (t < KV_)
        g_asum[(n * NCH_ + pc) * KV_ + t] = asb[0][t] + asb[1][t];
}

// ---------------- K2: ax GEMM + residual + sumsq partials ----------------
__global__ __launch_bounds__(256) void gv_K2(
    const float* __restrict__ x, const float* __restrict__ centers)
{
    __shared__ float a_s[KV_ * P_];     // 32 KB [k][p]
    __shared__ float asum_s[KV_];
    __shared__ float ssb[8][KV_];

    const int cc = blockIdx.x;          // 0..15 (32 channels)
    const int n  = blockIdx.y;
    const int t  = threadIdx.x;
    const int lane = t & 31, wid = t >> 5;

    {
        const float4* ap = (const float4*)(g_a + (size_t)n * KV_ * P_);
        float4* as4 = (float4*)a_s;
        #pragma unroll
        for (int i = 0; i < KV_ * P_ / 4 / 256; ++i)
            as4[t + i * 256] = ap[t + i * 256];
    }
    if (t < KV_) {
        float v = 0.f;
        #pragma unroll
        for (int pc = 0; pc < NCH_; ++pc) v += g_asum[(n * NCH_ + pc) * KV_ + t];
        asum_s[t] = v;
    }
    __syncthreads();

    const int cbase = cc * 32 + wid * 4;
    const float* xb = x + ((size_t)n * C_ + cbase) * P_;

    u64_t acc[4][KV_];
    #pragma unroll
    for (int ch = 0; ch < 4; ++ch)
        #pragma unroll
        for (int k = 0; k < KV_; ++k) acc[ch][k] = pack2(0.f, 0.f);

    #pragma unroll 2
    for (int it = 0; it < 8; ++it) {
        const int p0 = it * 128 + 4 * lane;
        float4 xv[4];
        #pragma unroll
        for (int ch = 0; ch < 4; ++ch)
            xv[ch] = *(const float4*)(xb + (size_t)ch * P_ + p0);
        u64_t a01[KV_], a23[KV_];
        #pragma unroll
        for (int k = 0; k < KV_; ++k) {
            float4 av = *(const float4*)(a_s + k * P_ + p0);
            a01[k] = pack2(av.x, av.y);
            a23[k] = pack2(av.z, av.w);
        }
        #pragma unroll
        for (int ch = 0; ch < 4; ++ch) {
            u64_t x01 = pack2(xv[ch].x, xv[ch].y);
            u64_t x23 = pack2(xv[ch].z, xv[ch].w);
            #pragma unroll
            for (int k = 0; k < KV_; ++k) {
                fma2(acc[ch][k], x01, a01[k]);
                fma2(acc[ch][k], x23, a23[k]);
            }
        }
    }

    float ssq[KV_];
    #pragma unroll
    for (int k = 0; k < KV_; ++k) ssq[k] = 0.f;

    #pragma unroll
    for (int ch = 0; ch < 4; ++ch) {
        #pragma unroll
        for (int k = 0; k < KV_; ++k) {
            float lo, hi; unpack2(acc[ch][k], lo, hi);
            float v = lo + hi;
            #pragma unroll
            for (int o = 16; o; o >>= 1) v += __shfl_xor_sync(0xffffffffu, v, o);
            if (lane == 0) {
                const int c = cbase + ch;
                float r = v - asum_s[k] * centers[k * C_ + c];
                g_r[((size_t)n * KV_ + k) * C_ + c] = r;
                ssq[k] += r * r;
            }
        }
    }
    if (lane == 0) {
        #pragma unroll
        for (int k = 0; k < KV_; ++k) ssb[wid][k] = ssq[k];
    }
    __syncthreads();
    if (t < KV_) {
        float v = 0.f;
        #pragma unroll
        for (int wg = 0; wg < 8; ++wg) v += ssb[wg][t];
        g_ss[((size_t)n * KV_ + t) * 16 + cc] = v;
    }
}

// ---------------- K3: normalize ----------------
__global__ __launch_bounds__(256) void gv_K3(float* __restrict__ out)
{
    const int k = blockIdx.x;
    const int n = blockIdx.y;
    const int t = threadIdx.x;

    float ss = 0.f;
    #pragma unroll
    for (int cc = 0; cc < 16; ++cc) ss += g_ss[((size_t)n * KV_ + k) * 16 + cc];
    float inv = 1.0f / fmaxf(sqrtf(ss), 1e-12f);

    const float* rp = g_r + ((size_t)n * KV_ + k) * C_;
    float* op = out + (size_t)n * (KV_ * C_) + k * C_;
    op[t]       = rp[t]       * inv;
    op[t + 256] = rp[t + 256] * inv;
}

extern "C" void kernel_launch(void* const* d_in, const int* in_sizes, int n_in,
                              void* d_out, int out_size) {
    const float* x       = (const float*)d_in[0];
    const float* conv_w  = (const float*)d_in[1];
    const float* conv_b  = (const float*)d_in[2];
    const float* centers = (const float*)d_in[3];
    float* out = (float*)d_out;

    gv_K1<<<dim3(NCH_, N_), 256>>>(x, conv_w, conv_b);
    gv_K2<<<dim3(16, N_), 256>>>(x, centers);
    gv_K3<<<dim3(KV_, N_), 256>>>(out);
}

// round 17
// speedup vs baseline: 1.4803x; 1.4803x over previous
#include <cuda_runtime.h>
#include <cuda_bf16.h>
#include <math.h>
#include <cstdint>

// GhostVLAD — round 17 (sm_103a). N=32, C=512, P=1024, KG=10, KV=8.
// K1 rebuilt as an exact shape-clone of the proven FMA-saturating K2:
//   grid (8,32) x 256 thr, ~66KB dyn smem (~2-3 CTAs/SM, ~4 warps/SMSP).
//   warp = one 64-channel group; lanes = 32 x 4 contiguous pixels
//   -> every LDG.128 is 512B warp-contiguous; 4-LDG batches + 80 FFMA2 blocks.
//   8-warp partial store to smem, 128-thread softmax tail.
// K2: R5-exact ax GEMM + residual + sumsq partials. K3: R5-exact normalize.

#define N_   32
#define C_   512
#define P_   1024
#define KG_  10
#define KV_  8
#define PB_  128                 // pixels per K1 CTA
#define NCH_ 8                   // K1 chunks per image

typedef unsigned long long u64_t;

__device__ __forceinline__ u64_t pack2(float lo, float hi) {
    u64_t r; asm("mov.b64 %0, {%1, %2};" : "=l"(r) : "f"(lo), "f"(hi)); return r;
}
__device__ __forceinline__ void unpack2(u64_t v, float& lo, float& hi) {
    asm("mov.b64 {%0, %1}, %2;" : "=f"(lo), "=f"(hi) : "l"(v));
}
__device__ __forceinline__ void fma2(u64_t& d, u64_t a, u64_t b) {
    asm("fma.rn.f32x2 %0, %1, %2, %0;" : "+l"(d) : "l"(a), "l"(b));
}

// scratch
__device__ float g_a[N_ * KV_ * P_];            // [n][k][p]
__device__ float g_asum[N_ * NCH_ * KV_];       // [n][chunk][k]
__device__ float g_r[N_ * KV_ * C_];            // residuals [n][k][c]
__device__ float g_ss[N_ * KV_ * 16];           // sumsq partials [n][k][cc]

// K1 dynamic smem layout (bytes)
#define WD_B    (C_ * 6 * 8)                    // 24576: [c][kp] pairs, stride 6
#define RED_B   (KG_ * 8 * PB_ * 4)             // 40960: [k*8+w][p]
#define ASB_B   (4 * KV_ * 4)                   // 128
#define BIAS_B  64
#define K1_SMEM (WD_B + RED_B + ASB_B + BIAS_B) // 65728

// ---------------- K1: logits + softmax (K2-isomorphic shape) ----------------
__global__ __launch_bounds__(256) void gv_K1(
    const float* __restrict__ x, const float* __restrict__ w,
    const float* __restrict__ bias)
{
    extern __shared__ char smraw[];
    u64_t* wd     = (u64_t*)smraw;                       // [c][kp], stride 6
    float* red    = (float*)(smraw + WD_B);              // [(k*8+w)][128]
    float* asb    = (float*)(smraw + WD_B + RED_B);      // [4][KV_]
    float* bias_s = (float*)(smraw + WD_B + RED_B + ASB_B);

    const int pb = blockIdx.x;       // 0..7 : 128-pixel block
    const int n  = blockIdx.y;
    const int t  = threadIdx.x;
    const int wid  = t >> 5;         // channel group 0..7 (64 ch each)
    const int lane = t & 31;         // 4 contiguous pixels per lane

    // div-free wd fill: wd[c*6+kp] = (w[2kp][c], w[2kp+1][c])
    #pragma unroll
    for (int cp0 = 0; cp0 < C_; cp0 += 256) {
        const int c = cp0 + t;
        #pragma unroll
        for (int kp = 0; kp < 5; ++kp)
            wd[c * 6 + kp] = pack2(w[(2 * kp) * C_ + c], w[(2 * kp + 1) * C_ + c]);
    }
    if (t < KG_) bias_s[t] = bias[t];
    __syncthreads();

    const int p0 = pb * PB_ + 4 * lane;
    const float* xp = x + ((size_t)n * C_ + wid * 64) * P_ + p0;

    // acc[kp][px] = (logit_{2kp}(px), logit_{2kp+1}(px)) : 40 registers
    u64_t acc[5][4];
    #pragma unroll
    for (int kp = 0; kp < 5; ++kp)
        #pragma unroll
        for (int px = 0; px < 4; ++px) acc[kp][px] = pack2(0.f, 0.f);

    // 16 blocks of 4 channels; 4 batched LDG.128 (each 512B warp-contiguous)
    #pragma unroll 2
    for (int b = 0; b < 16; ++b) {
        float4 xv[4];
        #pragma unroll
        for (int j = 0; j < 4; ++j)
            xv[j] = *(const float4*)(xp + (size_t)(b * 4 + j) * P_);
        #pragma unroll
        for (int j = 0; j < 4; ++j) {
            const int c = wid * 64 + b * 4 + j;       // warp-uniform -> broadcast LDS
            const ulonglong2* wr2 = (const ulonglong2*)(wd + c * 6);
            ulonglong2 w01 = wr2[0];
            ulonglong2 w23 = wr2[1];
            u64_t w4 = wd[c * 6 + 4];
            u64_t xd[4];
            xd[0] = pack2(xv[j].x, xv[j].x);
            xd[1] = pack2(xv[j].y, xv[j].y);
            xd[2] = pack2(xv[j].z, xv[j].z);
            xd[3] = pack2(xv[j].w, xv[j].w);
            #pragma unroll
            for (int px = 0; px < 4; ++px) {
                fma2(acc[0][px], xd[px], w01.x);
                fma2(acc[1][px], xd[px], w01.y);
                fma2(acc[2][px], xd[px], w23.x);
                fma2(acc[3][px], xd[px], w23.y);
                fma2(acc[4][px], xd[px], w4);
            }
        }
    }

    // store per-warp channel-group partials (conflict-free float4 rows)
    #pragma unroll
    for (int kp = 0; kp < 5; ++kp) {
        float4 lo4, hi4;
        unpack2(acc[kp][0], lo4.x, hi4.x);
        unpack2(acc[kp][1], lo4.y, hi4.y);
        unpack2(acc[kp][2], lo4.z, hi4.z);
        unpack2(acc[kp][3], lo4.w, hi4.w);
        *(float4*)(red + ((2 * kp) * 8 + wid) * PB_ + 4 * lane)     = lo4;
        *(float4*)(red + ((2 * kp + 1) * 8 + wid) * PB_ + 4 * lane) = hi4;
    }
    __syncthreads();

    // softmax per pixel: threads 0..127, p = t
    if (t < PB_) {
        const int p = t;
        const int lane2 = t & 31, wid2 = t >> 5;     // 4 warps
        float lg[KG_];
        #pragma unroll
        for (int k = 0; k < KG_; ++k) {
            float s = 0.f;
            #pragma unroll
            for (int cw = 0; cw < 8; ++cw) s += red[(k * 8 + cw) * PB_ + p];
            lg[k] = s + bias_s[k];
        }
        float m = lg[0];
        #pragma unroll
        for (int k = 1; k < KG_; ++k) m = fmaxf(m, lg[k]);
        float e[KG_], ssum = 0.f;
        #pragma unroll
        for (int k = 0; k < KG_; ++k) { e[k] = __expf(lg[k] - m); ssum += e[k]; }
        float inv = 1.0f / ssum;

        #pragma unroll
        for (int k = 0; k < KV_; ++k) {
            float a = e[k] * inv;
            g_a[((size_t)n * KV_ + k) * P_ + pb * PB_ + p] = a;
            float v = a;
            #pragma unroll
            for (int o = 16; o; o >>= 1) v += __shfl_xor_sync(0xffffffffu, v, o);
            if (lane2 == 0) asb[wid2 * KV_ + k] = v;
        }
    }
    __syncthreads();
    if (t < KV_) {
        float v = asb[t] + asb[KV_ + t] + asb[2 * KV_ + t] + asb[3 * KV_ + t];
        g_asum[(n * NCH_ + pb) * KV_ + t] = v;
    }
}

// ---------------- K2: ax GEMM + residual + sumsq partials (R5-exact) ----------------
__global__ __launch_bounds__(256) void gv_K2(
    const float* __restrict__ x, const float* __restrict__ centers)
{
    __shared__ float a_s[KV_ * P_];     // 32 KB [k][p]
    __shared__ float asum_s[KV_];
    __shared__ float ssb[8][KV_];

    const int cc = blockIdx.x;          // 0..15 (32 channels)
    const int n  = blockIdx.y;
    const int t  = threadIdx.x;
    const int lane = t & 31, wid = t >> 5;

    {
        const float4* ap = (const float4*)(g_a + (size_t)n * KV_ * P_);
        float4* as4 = (float4*)a_s;
        #pragma unroll
        for (int i = 0; i < KV_ * P_ / 4 / 256; ++i)
            as4[t + i * 256] = ap[t + i * 256];
    }
    if (t < KV_) {
        float v = 0.f;
        #pragma unroll
        for (int pc = 0; pc < NCH_; ++pc) v += g_asum[(n * NCH_ + pc) * KV_ + t];
        asum_s[t] = v;
    }
    __syncthreads();

    const int cbase = cc * 32 + wid * 4;
    const float* xb = x + ((size_t)n * C_ + cbase) * P_;

    u64_t acc[4][KV_];
    #pragma unroll
    for (int ch = 0; ch < 4; ++ch)
        #pragma unroll
        for (int k = 0; k < KV_; ++k) acc[ch][k] = pack2(0.f, 0.f);

    #pragma unroll 2
    for (int it = 0; it < 8; ++it) {
        const int p0 = it * 128 + 4 * lane;
        float4 xv[4];
        #pragma unroll
        for (int ch = 0; ch < 4; ++ch)
            xv[ch] = *(const float4*)(xb + (size_t)ch * P_ + p0);
        u64_t a01[KV_], a23[KV_];
        #pragma unroll
        for (int k = 0; k < KV_; ++k) {
            float4 av = *(const float4*)(a_s + k * P_ + p0);
            a01[k] = pack2(av.x, av.y);
            a23[k] = pack2(av.z, av.w);
        }
        #pragma unroll
        for (int ch = 0; ch < 4; ++ch) {
            u64_t x01 = pack2(xv[ch].x, xv[ch].y);
            u64_t x23 = pack2(xv[ch].z, xv[ch].w);
            #pragma unroll
            for (int k = 0; k < KV_; ++k) {
                fma2(acc[ch][k], x01, a01[k]);
                fma2(acc[ch][k], x23, a23[k]);
            }
        }
    }

    float ssq[KV_];
    #pragma unroll
    for (int k = 0; k < KV_; ++k) ssq[k] = 0.f;

    #pragma unroll
    for (int ch = 0; ch < 4; ++ch) {
        #pragma unroll
        for (int k = 0; k < KV_; ++k) {
            float lo, hi; unpack2(acc[ch][k], lo, hi);
            float v = lo + hi;
            #pragma unroll
            for (int o = 16; o; o >>= 1) v += __shfl_xor_sync(0xffffffffu, v, o);
            if (lane == 0) {
                const int c = cbase + ch;
                float r = v - asum_s[k] * centers[k * C_ + c];
                g_r[((size_t)n * KV_ + k) * C_ + c] = r;
                ssq[k] += r * r;
            }
        }
    }
    if (lane == 0) {
        #pragma unroll
        for (int k = 0; k < KV_; ++k) ssb[wid][k] = ssq[k];
    }
    __syncthreads();
    if (t < KV_) {
        float v = 0.f;
        #pragma unroll
        for (int wg = 0; wg < 8; ++wg) v += ssb[wg][t];
        g_ss[((size_t)n * KV_ + t) * 16 + cc] = v;
    }
}

// ---------------- K3: normalize (R5-exact) ----------------
__global__ __launch_bounds__(256) void gv_K3(float* __restrict__ out)
{
    const int k = blockIdx.x;
    const int n = blockIdx.y;
    const int t = threadIdx.x;

    float ss = 0.f;
    #pragma unroll
    for (int cc = 0; cc < 16; ++cc) ss += g_ss[((size_t)n * KV_ + k) * 16 + cc];
    float inv = 1.0f / fmaxf(sqrtf(ss), 1e-12f);

    const float* rp = g_r + ((size_t)n * KV_ + k) * C_;
    float* op = out + (size_t)n * (KV_ * C_) + k * C_;
    op[t]       = rp[t]       * inv;
    op[t + 256] = rp[t + 256] * inv;
}

extern "C" void kernel_launch(void* const* d_in, const int* in_sizes, int n_in,
                              void* d_out, int out_size) {
    const float* x       = (const float*)d_in[0];
    const float* conv_w  = (const float*)d_in[1];
    const float* conv_b  = (const float*)d_in[2];
    const float* centers = (const float*)d_in[3];
    float* out = (float*)d_out;

    cudaFuncSetAttribute(gv_K1,
                         cudaFuncAttributeMaxDynamicSharedMemorySize, K1_SMEM);

    gv_K1<<<dim3(NCH_, N_), 256, K1_SMEM>>>(x, conv_w, conv_b);
    gv_K2<<<dim3(16, N_), 256>>>(x, centers);
    gv_K3<<<dim3(KV_, N_), 256>>>(out);
}